// round 1
// baseline (speedup 1.0000x reference)
#include <cuda_runtime.h>
#include <cuda_bf16.h>
#include <cstdint>

#define M_ROWS 4096
#define VOCAB  32000
#define DIMD   1024

// ---------------- static scratch (allocation-free rule) ----------------
__device__ __nv_bfloat16 g_Tb[(size_t)VOCAB * DIMD];   // T bf16 [V][D]
__device__ __nv_bfloat16 g_Tt[(size_t)DIMD * VOCAB];   // T^T bf16 [D][V]
__device__ __nv_bfloat16 g_Xb[(size_t)M_ROWS * DIMD];  // X bf16
__device__ __nv_bfloat16 g_Wb[(size_t)DIMD * DIMD];    // W bf16 [e][d]
__device__ __nv_bfloat16 g_E [(size_t)M_ROWS * VOCAB]; // exp(sims) bf16
__device__ float         g_l [M_ROWS];                 // row sums of exp
__device__ __nv_bfloat16 g_Rb[(size_t)M_ROWS * DIMD];  // reprogrammed bf16
__device__ float         g_Y [(size_t)M_ROWS * DIMD];  // x + transformed

// ---------------- conversions ----------------
__global__ void k_cvt(const float* __restrict__ X, const float* __restrict__ W) {
  int stride = gridDim.x * blockDim.x;
  for (int i = blockIdx.x * blockDim.x + threadIdx.x; i < M_ROWS * DIMD; i += stride) {
    g_Xb[i] = __float2bfloat16(X[i]);
    if (i < DIMD * DIMD) g_Wb[i] = __float2bfloat16(W[i]);
    if (i < M_ROWS)      g_l[i]  = 0.f;
  }
}

__global__ void k_transpose(const float* __restrict__ T) {
  __shared__ float tile[32][33];
  int d0 = blockIdx.x * 32, v0 = blockIdx.y * 32;
  int tx = threadIdx.x, ty = threadIdx.y;
  #pragma unroll
  for (int j = 0; j < 32; j += 8) {
    float val = T[(size_t)(v0 + ty + j) * DIMD + d0 + tx];
    tile[ty + j][tx] = val;
    g_Tb[(size_t)(v0 + ty + j) * DIMD + d0 + tx] = __float2bfloat16(val);
  }
  __syncthreads();
  #pragma unroll
  for (int j = 0; j < 32; j += 8)
    g_Tt[(size_t)(d0 + ty + j) * VOCAB + v0 + tx] = __float2bfloat16(tile[tx][ty + j]);
}

// ---------------- mma.sync GEMM ----------------
// Tiles: BM=128, BN=128, BK=32. 8 warps (2x4), warp tile 64x32, m16n8k16 bf16.
// SMEM tile row = 64B (4 x 16B chunks), XOR swizzle chunk^=((row>>1)&3):
// optimal 2-phase ldmatrix, conflict-free-enough stores.

__device__ __forceinline__ int swz(int r, int c) {
  return r * 64 + ((c ^ ((r >> 1) & 3)) << 4);
}
__device__ __forceinline__ unsigned sptr(const void* p) {
  return (unsigned)__cvta_generic_to_shared(p);
}

// EPI: 0 = GEMM1 (Xb@Tb^T -> exp -> g_E + rowsum atomics)
//      1 = GEMM2 (E@Tt^T(=T) -> /l -> g_Rb)
//      2 = GEMM3 (Rb@Wb^T + bias + X -> g_Y)
template<int EPI>
__global__ __launch_bounds__(256, 2)
void k_gemm(const float* __restrict__ Xf, const float* __restrict__ bias) {
  constexpr int KD  = (EPI == 1) ? VOCAB : DIMD;
  constexpr int LDC = (EPI == 0) ? VOCAB : DIMD;
  const __nv_bfloat16* __restrict__ A  = (EPI == 0) ? g_Xb : (EPI == 1) ? g_E  : g_Rb;
  const __nv_bfloat16* __restrict__ Bm = (EPI == 0) ? g_Tb : (EPI == 1) ? g_Tt : g_Wb;

  __shared__ __align__(16) uint8_t smA[2][128 * 64];
  __shared__ __align__(16) uint8_t smB[2][128 * 64];

  const int t    = threadIdx.x;
  const int row0 = blockIdx.y * 128;
  const int col0 = blockIdx.x * 128;

  // gmem->smem: each thread owns 16B chunks t and t+256 of each 8KB tile
  const int r0 = t >> 2, c0 = t & 3;             // chunk t: row r0, chunk-col c0
  const __nv_bfloat16* pA0 = A  + (size_t)(row0 + r0)      * KD + c0 * 8;
  const __nv_bfloat16* pA1 = A  + (size_t)(row0 + r0 + 64) * KD + c0 * 8;
  const __nv_bfloat16* pB0 = Bm + (size_t)(col0 + r0)      * KD + c0 * 8;
  const __nv_bfloat16* pB1 = Bm + (size_t)(col0 + r0 + 64) * KD + c0 * 8;
  const int s0 = swz(r0, c0), s1 = swz(r0 + 64, c0);

  const int warp = t >> 5, lane = t & 31;
  const int wm = warp >> 2, wn = warp & 3;

  float acc[4][4][4];
  #pragma unroll
  for (int i = 0; i < 4; i++)
    #pragma unroll
    for (int j = 0; j < 4; j++)
      #pragma unroll
      for (int k = 0; k < 4; k++) acc[i][j][k] = 0.f;

  const int nk = KD / 32;

  uint4 va0 = *(const uint4*)pA0;
  uint4 va1 = *(const uint4*)pA1;
  uint4 vb0 = *(const uint4*)pB0;
  uint4 vb1 = *(const uint4*)pB1;
  *(uint4*)(smA[0] + s0) = va0;
  *(uint4*)(smA[0] + s1) = va1;
  *(uint4*)(smB[0] + s0) = vb0;
  *(uint4*)(smB[0] + s1) = vb1;
  __syncthreads();

  for (int kt = 0; kt < nk; ++kt) {
    const int cur = kt & 1;
    if (kt + 1 < nk) {
      pA0 += 32; pA1 += 32; pB0 += 32; pB1 += 32;
      va0 = *(const uint4*)pA0;
      va1 = *(const uint4*)pA1;
      vb0 = *(const uint4*)pB0;
      vb1 = *(const uint4*)pB1;
    }
    const uint8_t* sA = smA[cur];
    const uint8_t* sB = smB[cur];
    #pragma unroll
    for (int ks = 0; ks < 2; ++ks) {
      unsigned a[4][4], bfr[2][4];
      const int rr = lane & 15, cc = ks * 2 + (lane >> 4);
      #pragma unroll
      for (int im = 0; im < 4; ++im) {
        unsigned addr = sptr(sA + swz(wm * 64 + im * 16 + rr, cc));
        asm volatile("ldmatrix.sync.aligned.m8n8.x4.shared.b16 {%0,%1,%2,%3}, [%4];"
          : "=r"(a[im][0]), "=r"(a[im][1]), "=r"(a[im][2]), "=r"(a[im][3]) : "r"(addr));
      }
      #pragma unroll
      for (int j = 0; j < 2; ++j) {
        unsigned addr = sptr(sB + swz(wn * 32 + j * 16 + rr, cc));
        asm volatile("ldmatrix.sync.aligned.m8n8.x4.shared.b16 {%0,%1,%2,%3}, [%4];"
          : "=r"(bfr[j][0]), "=r"(bfr[j][1]), "=r"(bfr[j][2]), "=r"(bfr[j][3]) : "r"(addr));
      }
      #pragma unroll
      for (int im = 0; im < 4; ++im)
        #pragma unroll
        for (int in = 0; in < 4; ++in) {
          unsigned bb0 = bfr[in >> 1][in & 1];
          unsigned bb1 = bfr[in >> 1][(in & 1) + 2];
          asm volatile("mma.sync.aligned.m16n8k16.row.col.f32.bf16.bf16.f32 "
            "{%0,%1,%2,%3}, {%4,%5,%6,%7}, {%8,%9}, {%0,%1,%2,%3};"
            : "+f"(acc[im][in][0]), "+f"(acc[im][in][1]),
              "+f"(acc[im][in][2]), "+f"(acc[im][in][3])
            : "r"(a[im][0]), "r"(a[im][1]), "r"(a[im][2]), "r"(a[im][3]),
              "r"(bb0), "r"(bb1));
        }
    }
    if (kt + 1 < nk) {
      const int nxt = cur ^ 1;
      *(uint4*)(smA[nxt] + s0) = va0;
      *(uint4*)(smA[nxt] + s1) = va1;
      *(uint4*)(smB[nxt] + s0) = vb0;
      *(uint4*)(smB[nxt] + s1) = vb1;
      __syncthreads();
    }
  }

  // ---------------- epilogues ----------------
  const int lr = lane >> 2, lc = (lane & 3) * 2;
  const int rbase = row0 + wm * 64;
  const int cbase = col0 + wn * 32;

  if (EPI == 0) {
    #pragma unroll
    for (int im = 0; im < 4; ++im) {
      float rs0 = 0.f, rs1 = 0.f;
      #pragma unroll
      for (int in = 0; in < 4; ++in) {
        float e0 = expf(acc[im][in][0]);
        float e1 = expf(acc[im][in][1]);
        float e2 = expf(acc[im][in][2]);
        float e3 = expf(acc[im][in][3]);
        int r = rbase + im * 16 + lr;
        int c = cbase + in * 8 + lc;
        __nv_bfloat162 p01, p23;
        p01.x = __float2bfloat16(e0); p01.y = __float2bfloat16(e1);
        p23.x = __float2bfloat16(e2); p23.y = __float2bfloat16(e3);
        *(__nv_bfloat162*)(g_E + (size_t)r       * LDC + c) = p01;
        *(__nv_bfloat162*)(g_E + (size_t)(r + 8) * LDC + c) = p23;
        rs0 += e0 + e1; rs1 += e2 + e3;
      }
      rs0 += __shfl_xor_sync(0xffffffffu, rs0, 1);
      rs0 += __shfl_xor_sync(0xffffffffu, rs0, 2);
      rs1 += __shfl_xor_sync(0xffffffffu, rs1, 1);
      rs1 += __shfl_xor_sync(0xffffffffu, rs1, 2);
      if ((lane & 3) == 0) {
        atomicAdd(&g_l[rbase + im * 16 + lr],     rs0);
        atomicAdd(&g_l[rbase + im * 16 + lr + 8], rs1);
      }
    }
  } else if (EPI == 1) {
    #pragma unroll
    for (int im = 0; im < 4; ++im) {
      int r = rbase + im * 16 + lr;
      float inv0 = 1.f / g_l[r];
      float inv1 = 1.f / g_l[r + 8];
      #pragma unroll
      for (int in = 0; in < 4; ++in) {
        int c = cbase + in * 8 + lc;
        __nv_bfloat162 p01, p23;
        p01.x = __float2bfloat16(acc[im][in][0] * inv0);
        p01.y = __float2bfloat16(acc[im][in][1] * inv0);
        p23.x = __float2bfloat16(acc[im][in][2] * inv1);
        p23.y = __float2bfloat16(acc[im][in][3] * inv1);
        *(__nv_bfloat162*)(g_Rb + (size_t)r       * LDC + c) = p01;
        *(__nv_bfloat162*)(g_Rb + (size_t)(r + 8) * LDC + c) = p23;
      }
    }
  } else {
    #pragma unroll
    for (int im = 0; im < 4; ++im) {
      int r = rbase + im * 16 + lr;
      #pragma unroll
      for (int in = 0; in < 4; ++in) {
        int c = cbase + in * 8 + lc;
        g_Y[(size_t)r * DIMD + c]         = acc[im][in][0] + bias[c]     + Xf[(size_t)r * DIMD + c];
        g_Y[(size_t)r * DIMD + c + 1]     = acc[im][in][1] + bias[c + 1] + Xf[(size_t)r * DIMD + c + 1];
        g_Y[(size_t)(r + 8) * DIMD + c]     = acc[im][in][2] + bias[c]     + Xf[(size_t)(r + 8) * DIMD + c];
        g_Y[(size_t)(r + 8) * DIMD + c + 1] = acc[im][in][3] + bias[c + 1] + Xf[(size_t)(r + 8) * DIMD + c + 1];
      }
    }
  }
}

// ---------------- layernorm ----------------
__global__ void k_ln(const float* __restrict__ gamma, const float* __restrict__ beta,
                     float* __restrict__ out) {
  int row  = blockIdx.x * 8 + (threadIdx.x >> 5);
  int lane = threadIdx.x & 31;
  const float* y = g_Y + (size_t)row * DIMD;
  float v[32], s = 0.f;
  #pragma unroll
  for (int i = 0; i < 32; ++i) { v[i] = y[lane + i * 32]; s += v[i]; }
  #pragma unroll
  for (int o = 16; o > 0; o >>= 1) s += __shfl_xor_sync(0xffffffffu, s, o);
  float mu = s * (1.f / DIMD);
  float q = 0.f;
  #pragma unroll
  for (int i = 0; i < 32; ++i) { float d = v[i] - mu; q += d * d; }
  #pragma unroll
  for (int o = 16; o > 0; o >>= 1) q += __shfl_xor_sync(0xffffffffu, q, o);
  float rstd = rsqrtf(q * (1.f / DIMD) + 1e-5f);
  #pragma unroll
  for (int i = 0; i < 32; ++i) {
    int c = lane + i * 32;
    out[(size_t)row * DIMD + c] = (v[i] - mu) * rstd * gamma[c] + beta[c];
  }
}

// ---------------- launch ----------------
extern "C" void kernel_launch(void* const* d_in, const int* in_sizes, int n_in,
                              void* d_out, int out_size) {
  const float* X     = (const float*)d_in[0];
  const float* T     = (const float*)d_in[1];
  const float* W     = (const float*)d_in[2];
  const float* bias  = (const float*)d_in[3];
  const float* gamma = (const float*)d_in[4];
  const float* beta  = (const float*)d_in[5];
  float* out = (float*)d_out;

  k_cvt<<<2048, 512>>>(X, W);
  k_transpose<<<dim3(DIMD / 32, VOCAB / 32), dim3(32, 8)>>>(T);
  k_gemm<0><<<dim3(VOCAB / 128, M_ROWS / 128), 256>>>(nullptr, nullptr);
  k_gemm<1><<<dim3(DIMD  / 128, M_ROWS / 128), 256>>>(nullptr, nullptr);
  k_gemm<2><<<dim3(DIMD  / 128, M_ROWS / 128), 256>>>(X, bias);
  k_ln<<<M_ROWS / 8, 256>>>(gamma, beta, out);
}

// round 2
// speedup vs baseline: 1.0017x; 1.0017x over previous
#include <cuda_runtime.h>
#include <cuda_bf16.h>
#include <cstdint>

#define M_ROWS 4096
#define VOCAB  32000
#define DIMD   1024

// ---------------- static scratch (allocation-free rule) ----------------
__device__ __nv_bfloat16 g_Tb[(size_t)VOCAB * DIMD];   // T bf16 [V][D]
__device__ __nv_bfloat16 g_Tt[(size_t)DIMD * VOCAB];   // T^T bf16 [D][V]
__device__ __nv_bfloat16 g_Xb[(size_t)M_ROWS * DIMD];  // X bf16
__device__ __nv_bfloat16 g_Wb[(size_t)DIMD * DIMD];    // W bf16 [e][d]
__device__ __nv_bfloat16 g_E [(size_t)M_ROWS * VOCAB]; // exp(sims) bf16
__device__ float         g_l [M_ROWS];                 // row sums of exp
__device__ __nv_bfloat16 g_Rb[(size_t)M_ROWS * DIMD];  // reprogrammed bf16
__device__ float         g_Y [(size_t)M_ROWS * DIMD];  // x + transformed

// ---------------- conversions ----------------
__global__ void k_cvt(const float* __restrict__ X, const float* __restrict__ W) {
  int stride = gridDim.x * blockDim.x;
  for (int i = blockIdx.x * blockDim.x + threadIdx.x; i < M_ROWS * DIMD; i += stride) {
    g_Xb[i] = __float2bfloat16(X[i]);
    if (i < DIMD * DIMD) g_Wb[i] = __float2bfloat16(W[i]);
    if (i < M_ROWS)      g_l[i]  = 0.f;
  }
}

__global__ void k_transpose(const float* __restrict__ T) {
  __shared__ float tile[32][33];
  int d0 = blockIdx.x * 32, v0 = blockIdx.y * 32;
  int tx = threadIdx.x, ty = threadIdx.y;
  #pragma unroll
  for (int j = 0; j < 32; j += 8) {
    float val = T[(size_t)(v0 + ty + j) * DIMD + d0 + tx];
    tile[ty + j][tx] = val;
    g_Tb[(size_t)(v0 + ty + j) * DIMD + d0 + tx] = __float2bfloat16(val);
  }
  __syncthreads();
  #pragma unroll
  for (int j = 0; j < 32; j += 8)
    g_Tt[(size_t)(d0 + ty + j) * VOCAB + v0 + tx] = __float2bfloat16(tile[tx][ty + j]);
}

// ---------------- mma.sync GEMM ----------------
// Tiles: BM=128, BN=128, BK=32. 8 warps (2x4), warp tile 64x32, m16n8k16 bf16.
// SMEM tile row = 64B (4 x 16B chunks), XOR swizzle chunk^=((row>>1)&3):
// optimal 2-phase ldmatrix, conflict-free-enough stores.

__device__ __forceinline__ int swz(int r, int c) {
  return r * 64 + ((c ^ ((r >> 1) & 3)) << 4);
}
__device__ __forceinline__ unsigned sptr(const void* p) {
  return (unsigned)__cvta_generic_to_shared(p);
}

// EPI: 0 = GEMM1 (Xb@Tb^T -> exp -> g_E + rowsum atomics)
//      1 = GEMM2 (E@Tt^T(=T) -> /l -> g_Rb)
//      2 = GEMM3 (Rb@Wb^T + bias + X -> g_Y)
template<int EPI>
__global__ __launch_bounds__(256, 2)
void k_gemm(const float* __restrict__ Xf, const float* __restrict__ bias) {
  constexpr int KD  = (EPI == 1) ? VOCAB : DIMD;
  constexpr int LDC = (EPI == 0) ? VOCAB : DIMD;
  const __nv_bfloat16* __restrict__ A  = (EPI == 0) ? g_Xb : (EPI == 1) ? g_E  : g_Rb;
  const __nv_bfloat16* __restrict__ Bm = (EPI == 0) ? g_Tb : (EPI == 1) ? g_Tt : g_Wb;

  __shared__ __align__(16) uint8_t smA[2][128 * 64];
  __shared__ __align__(16) uint8_t smB[2][128 * 64];

  const int t    = threadIdx.x;
  const int row0 = blockIdx.y * 128;
  const int col0 = blockIdx.x * 128;

  // gmem->smem: each thread owns 16B chunks t and t+256 of each 8KB tile
  const int r0 = t >> 2, c0 = t & 3;             // chunk t: row r0, chunk-col c0
  const __nv_bfloat16* pA0 = A  + (size_t)(row0 + r0)      * KD + c0 * 8;
  const __nv_bfloat16* pA1 = A  + (size_t)(row0 + r0 + 64) * KD + c0 * 8;
  const __nv_bfloat16* pB0 = Bm + (size_t)(col0 + r0)      * KD + c0 * 8;
  const __nv_bfloat16* pB1 = Bm + (size_t)(col0 + r0 + 64) * KD + c0 * 8;
  const int s0 = swz(r0, c0), s1 = swz(r0 + 64, c0);

  const int warp = t >> 5, lane = t & 31;
  const int wm = warp >> 2, wn = warp & 3;

  float acc[4][4][4];
  #pragma unroll
  for (int i = 0; i < 4; i++)
    #pragma unroll
    for (int j = 0; j < 4; j++)
      #pragma unroll
      for (int k = 0; k < 4; k++) acc[i][j][k] = 0.f;

  const int nk = KD / 32;

  uint4 va0 = *(const uint4*)pA0;
  uint4 va1 = *(const uint4*)pA1;
  uint4 vb0 = *(const uint4*)pB0;
  uint4 vb1 = *(const uint4*)pB1;
  *(uint4*)(smA[0] + s0) = va0;
  *(uint4*)(smA[0] + s1) = va1;
  *(uint4*)(smB[0] + s0) = vb0;
  *(uint4*)(smB[0] + s1) = vb1;
  __syncthreads();

  for (int kt = 0; kt < nk; ++kt) {
    const int cur = kt & 1;
    if (kt + 1 < nk) {
      pA0 += 32; pA1 += 32; pB0 += 32; pB1 += 32;
      va0 = *(const uint4*)pA0;
      va1 = *(const uint4*)pA1;
      vb0 = *(const uint4*)pB0;
      vb1 = *(const uint4*)pB1;
    }
    const uint8_t* sA = smA[cur];
    const uint8_t* sB = smB[cur];
    #pragma unroll
    for (int ks = 0; ks < 2; ++ks) {
      unsigned a[4][4], bfr[2][4];
      const int rr = lane & 15, cc = ks * 2 + (lane >> 4);
      #pragma unroll
      for (int im = 0; im < 4; ++im) {
        unsigned addr = sptr(sA + swz(wm * 64 + im * 16 + rr, cc));
        asm volatile("ldmatrix.sync.aligned.m8n8.x4.shared.b16 {%0,%1,%2,%3}, [%4];"
          : "=r"(a[im][0]), "=r"(a[im][1]), "=r"(a[im][2]), "=r"(a[im][3]) : "r"(addr));
      }
      #pragma unroll
      for (int j = 0; j < 2; ++j) {
        unsigned addr = sptr(sB + swz(wn * 32 + j * 16 + rr, cc));
        asm volatile("ldmatrix.sync.aligned.m8n8.x4.shared.b16 {%0,%1,%2,%3}, [%4];"
          : "=r"(bfr[j][0]), "=r"(bfr[j][1]), "=r"(bfr[j][2]), "=r"(bfr[j][3]) : "r"(addr));
      }
      #pragma unroll
      for (int im = 0; im < 4; ++im)
        #pragma unroll
        for (int in = 0; in < 4; ++in) {
          unsigned bb0 = bfr[in >> 1][in & 1];
          unsigned bb1 = bfr[in >> 1][(in & 1) + 2];
          asm volatile("mma.sync.aligned.m16n8k16.row.col.f32.bf16.bf16.f32 "
            "{%0,%1,%2,%3}, {%4,%5,%6,%7}, {%8,%9}, {%0,%1,%2,%3};"
            : "+f"(acc[im][in][0]), "+f"(acc[im][in][1]),
              "+f"(acc[im][in][2]), "+f"(acc[im][in][3])
            : "r"(a[im][0]), "r"(a[im][1]), "r"(a[im][2]), "r"(a[im][3]),
              "r"(bb0), "r"(bb1));
        }
    }
    if (kt + 1 < nk) {
      const int nxt = cur ^ 1;
      *(uint4*)(smA[nxt] + s0) = va0;
      *(uint4*)(smA[nxt] + s1) = va1;
      *(uint4*)(smB[nxt] + s0) = vb0;
      *(uint4*)(smB[nxt] + s1) = vb1;
      __syncthreads();
    }
  }

  // ---------------- epilogues ----------------
  const int lr = lane >> 2, lc = (lane & 3) * 2;
  const int rbase = row0 + wm * 64;
  const int cbase = col0 + wn * 32;

  if (EPI == 0) {
    #pragma unroll
    for (int im = 0; im < 4; ++im) {
      float rs0 = 0.f, rs1 = 0.f;
      #pragma unroll
      for (int in = 0; in < 4; ++in) {
        float e0 = expf(acc[im][in][0]);
        float e1 = expf(acc[im][in][1]);
        float e2 = expf(acc[im][in][2]);
        float e3 = expf(acc[im][in][3]);
        int r = rbase + im * 16 + lr;
        int c = cbase + in * 8 + lc;
        __nv_bfloat162 p01, p23;
        p01.x = __float2bfloat16(e0); p01.y = __float2bfloat16(e1);
        p23.x = __float2bfloat16(e2); p23.y = __float2bfloat16(e3);
        *(__nv_bfloat162*)(g_E + (size_t)r       * LDC + c) = p01;
        *(__nv_bfloat162*)(g_E + (size_t)(r + 8) * LDC + c) = p23;
        rs0 += e0 + e1; rs1 += e2 + e3;
      }
      rs0 += __shfl_xor_sync(0xffffffffu, rs0, 1);
      rs0 += __shfl_xor_sync(0xffffffffu, rs0, 2);
      rs1 += __shfl_xor_sync(0xffffffffu, rs1, 1);
      rs1 += __shfl_xor_sync(0xffffffffu, rs1, 2);
      if ((lane & 3) == 0) {
        atomicAdd(&g_l[rbase + im * 16 + lr],     rs0);
        atomicAdd(&g_l[rbase + im * 16 + lr + 8], rs1);
      }
    }
  } else if (EPI == 1) {
    #pragma unroll
    for (int im = 0; im < 4; ++im) {
      int r = rbase + im * 16 + lr;
      float inv0 = 1.f / g_l[r];
      float inv1 = 1.f / g_l[r + 8];
      #pragma unroll
      for (int in = 0; in < 4; ++in) {
        int c = cbase + in * 8 + lc;
        __nv_bfloat162 p01, p23;
        p01.x = __float2bfloat16(acc[im][in][0] * inv0);
        p01.y = __float2bfloat16(acc[im][in][1] * inv0);
        p23.x = __float2bfloat16(acc[im][in][2] * inv1);
        p23.y = __float2bfloat16(acc[im][in][3] * inv1);
        *(__nv_bfloat162*)(g_Rb + (size_t)r       * LDC + c) = p01;
        *(__nv_bfloat162*)(g_Rb + (size_t)(r + 8) * LDC + c) = p23;
      }
    }
  } else {
    #pragma unroll
    for (int im = 0; im < 4; ++im) {
      int r = rbase + im * 16 + lr;
      #pragma unroll
      for (int in = 0; in < 4; ++in) {
        int c = cbase + in * 8 + lc;
        g_Y[(size_t)r * DIMD + c]         = acc[im][in][0] + bias[c]     + Xf[(size_t)r * DIMD + c];
        g_Y[(size_t)r * DIMD + c + 1]     = acc[im][in][1] + bias[c + 1] + Xf[(size_t)r * DIMD + c + 1];
        g_Y[(size_t)(r + 8) * DIMD + c]     = acc[im][in][2] + bias[c]     + Xf[(size_t)(r + 8) * DIMD + c];
        g_Y[(size_t)(r + 8) * DIMD + c + 1] = acc[im][in][3] + bias[c + 1] + Xf[(size_t)(r + 8) * DIMD + c + 1];
      }
    }
  }
}

// ---------------- layernorm ----------------
__global__ void k_ln(const float* __restrict__ gamma, const float* __restrict__ beta,
                     float* __restrict__ out) {
  int row  = blockIdx.x * 8 + (threadIdx.x >> 5);
  int lane = threadIdx.x & 31;
  const float* y = g_Y + (size_t)row * DIMD;
  float v[32], s = 0.f;
  #pragma unroll
  for (int i = 0; i < 32; ++i) { v[i] = y[lane + i * 32]; s += v[i]; }
  #pragma unroll
  for (int o = 16; o > 0; o >>= 1) s += __shfl_xor_sync(0xffffffffu, s, o);
  float mu = s * (1.f / DIMD);
  float q = 0.f;
  #pragma unroll
  for (int i = 0; i < 32; ++i) { float d = v[i] - mu; q += d * d; }
  #pragma unroll
  for (int o = 16; o > 0; o >>= 1) q += __shfl_xor_sync(0xffffffffu, q, o);
  float rstd = rsqrtf(q * (1.f / DIMD) + 1e-5f);
  #pragma unroll
  for (int i = 0; i < 32; ++i) {
    int c = lane + i * 32;
    out[(size_t)row * DIMD + c] = (v[i] - mu) * rstd * gamma[c] + beta[c];
  }
}

// ---------------- launch ----------------
extern "C" void kernel_launch(void* const* d_in, const int* in_sizes, int n_in,
                              void* d_out, int out_size) {
  const float* X     = (const float*)d_in[0];
  const float* T     = (const float*)d_in[1];
  const float* W     = (const float*)d_in[2];
  const float* bias  = (const float*)d_in[3];
  const float* gamma = (const float*)d_in[4];
  const float* beta  = (const float*)d_in[5];
  float* out = (float*)d_out;

  k_cvt<<<2048, 512>>>(X, W);
  k_transpose<<<dim3(DIMD / 32, VOCAB / 32), dim3(32, 8)>>>(T);
  k_gemm<0><<<dim3(VOCAB / 128, M_ROWS / 128), 256>>>(nullptr, nullptr);
  k_gemm<1><<<dim3(DIMD  / 128, M_ROWS / 128), 256>>>(nullptr, nullptr);
  k_gemm<2><<<dim3(DIMD  / 128, M_ROWS / 128), 256>>>(X, bias);
  k_ln<<<M_ROWS / 8, 256>>>(gamma, beta, out);
}

// round 4
// speedup vs baseline: 1.1290x; 1.1270x over previous
#include <cuda_runtime.h>
#include <cuda_bf16.h>
#include <cstdint>

#define M_ROWS 4096
#define VOCAB  32000
#define DIMD   1024

// ---------------- static scratch (allocation-free rule) ----------------
__device__ __nv_bfloat16 g_Tb[(size_t)VOCAB * DIMD];   // T bf16 [V][D] (K-major, K=d)
__device__ __nv_bfloat16 g_Tt[(size_t)DIMD * VOCAB];   // T^T bf16 [D][V] (K-major, K=v)
__device__ __nv_bfloat16 g_Xb[(size_t)M_ROWS * DIMD];  // X bf16
__device__ __nv_bfloat16 g_Wb[(size_t)DIMD * DIMD];    // W bf16 [e][d]
__device__ __nv_bfloat16 g_E [(size_t)M_ROWS * VOCAB]; // exp(sims) bf16
__device__ float         g_l [M_ROWS];                 // row sums of exp
__device__ __nv_bfloat16 g_Rb[(size_t)M_ROWS * DIMD];  // reprogrammed bf16
__device__ float         g_Y [(size_t)M_ROWS * DIMD];  // x + transformed

// ---------------- helpers ----------------
__device__ __forceinline__ uint32_t smem_u32(const void* p) {
  uint32_t a;
  asm("{ .reg .u64 t; cvta.to.shared.u64 t, %1; cvt.u32.u64 %0, t; }" : "=r"(a) : "l"(p));
  return a;
}
#define CPASYNC(dst, src) \
  asm volatile("cp.async.cg.shared.global [%0], [%1], 16;" :: "r"(dst), "l"(src) : "memory")
#define CPCOMMIT() asm volatile("cp.async.commit_group;" ::: "memory")
#define CPWAIT2()  asm volatile("cp.async.wait_group 2;" ::: "memory")

// fast exp: e^x = 2^(x*log2e); magic-number round, deg-4 poly for 2^f, exponent splice
__device__ __forceinline__ float fexp(float x) {
  float t = x * 1.4426950408889634f;
  float r = t + 12582912.0f;                 // round-to-nearest-int (|t| << 2^21)
  int   ib = __float_as_int(r);
  float f = t - (r - 12582912.0f);
  float p = 0.00961812911f;
  p = fmaf(p, f, 0.05550410866f);
  p = fmaf(p, f, 0.24022650696f);
  p = fmaf(p, f, 0.69314718056f);
  p = fmaf(p, f, 1.0f);
  return p * __int_as_float((ib + 127) << 23);
}

// ---------------- conversions ----------------
__global__ void k_cvt(const float* __restrict__ X, const float* __restrict__ W) {
  int stride = gridDim.x * blockDim.x;
  for (int i = blockIdx.x * blockDim.x + threadIdx.x; i < M_ROWS * DIMD; i += stride) {
    g_Xb[i] = __float2bfloat16(X[i]);
    if (i < DIMD * DIMD) g_Wb[i] = __float2bfloat16(W[i]);
    if (i < M_ROWS)      g_l[i]  = 0.f;
  }
}

__global__ void k_transpose(const float* __restrict__ T) {
  __shared__ float tile[32][33];
  int d0 = blockIdx.x * 32, v0 = blockIdx.y * 32;
  int tx = threadIdx.x, ty = threadIdx.y;
  #pragma unroll
  for (int j = 0; j < 32; j += 8) {
    float val = T[(size_t)(v0 + ty + j) * DIMD + d0 + tx];
    tile[ty + j][tx] = val;
    g_Tb[(size_t)(v0 + ty + j) * DIMD + d0 + tx] = __float2bfloat16(val);
  }
  __syncthreads();
  #pragma unroll
  for (int j = 0; j < 32; j += 8)
    g_Tt[(size_t)(d0 + ty + j) * VOCAB + v0 + tx] = __float2bfloat16(tile[tx][ty + j]);
}

// ---------------- mma.sync GEMM, CTA 128x256, BK=64, 8 warps (2x4), warp tile 64x64 ----
// smem stage: A[128][64] bf16 (16KB) + B[256][64] bf16 (32KB) = 48KB; 3 stages (cp.async).
// Row = 128B = 8 x 16B chunks; phys chunk = c ^ (row & 7) -> conflict-free ldmatrix+stores.
// EPI: 0 = GEMM1 (Xb @ Tb^T -> fexp -> g_E + rowsum atomics)
//      1 = GEMM2 (E @ Tt^T -> * 1/l -> g_Rb)
//      2 = GEMM3 (Rb @ Wb^T + bias + X -> g_Y)
#define STAGE_BYTES 49152
#define SMEM_DYN (3 * STAGE_BYTES + 1024)

template<int EPI>
__global__ __launch_bounds__(256, 1)
void k_g(const float* __restrict__ Xf, const float* __restrict__ bias) {
  extern __shared__ __align__(16) uint8_t dyn[];
  const uint32_t tiles = (smem_u32(dyn) + 1023u) & ~1023u;

  const int t = threadIdx.x, warp = t >> 5, lane = t & 31;
  const int wm = warp >> 2, wn = warp & 3;          // 2 x 4 warps
  const int row0 = blockIdx.y * 128;
  const int col0 = blockIdx.x * 256;

  const __nv_bfloat16* __restrict__ A;
  const __nv_bfloat16* __restrict__ B;
  int lda, ldb, NK;
  if (EPI == 0)      { A = g_Xb; lda = DIMD;  B = g_Tb; ldb = DIMD;  NK = DIMD / 64;  }
  else if (EPI == 1) { A = g_E;  lda = VOCAB; B = g_Tt; ldb = VOCAB; NK = VOCAB / 64; }
  else               { A = g_Rb; lda = DIMD;  B = g_Wb; ldb = DIMD;  NK = DIMD / 64;  }

  // ---- gmem->smem mapping: thread t loads row r=t>>3 (+32j), 16B chunk c=t&7
  const int r = t >> 3, c = t & 7;
  const int phys = (c ^ (r & 7)) << 4;                 // swizzled chunk byte offset
  const uint8_t* gA = (const uint8_t*)(A + (size_t)(row0 + r) * lda + c * 8);
  const uint8_t* gB = (const uint8_t*)(B + (size_t)(col0 + r) * ldb + c * 8);
  const size_t sgA = (size_t)32 * lda * 2;             // 32 rows in bytes
  const size_t sgB = (size_t)32 * ldb * 2;

  auto load_tile = [&](int s, int kt) {
    const uint32_t a0 = tiles + (uint32_t)s * STAGE_BYTES;
    const uint32_t b0 = a0 + 16384;
    const uint8_t* pa = gA + (size_t)kt * 128;
    const uint8_t* pb = gB + (size_t)kt * 128;
    #pragma unroll
    for (int j = 0; j < 4; ++j)
      CPASYNC(a0 + (uint32_t)(r + 32 * j) * 128 + phys, pa + (size_t)j * sgA);
    #pragma unroll
    for (int j = 0; j < 8; ++j)
      CPASYNC(b0 + (uint32_t)(r + 32 * j) * 128 + phys, pb + (size_t)j * sgB);
  };

  float acc[4][8][4];
  #pragma unroll
  for (int i = 0; i < 4; ++i)
    #pragma unroll
    for (int j = 0; j < 8; ++j)
      #pragma unroll
      for (int q = 0; q < 4; ++q) acc[i][j][q] = 0.f;

  // ldmatrix per-lane constants
  const int rr = lane & 15, hi = lane >> 4, xr = rr & 7;
  uint32_t abase[4], bbase[4];
  #pragma unroll
  for (int i = 0; i < 4; ++i) {
    abase[i] = (uint32_t)(wm * 64 + i * 16 + rr) * 128;
    bbase[i] = (uint32_t)(wn * 64 + i * 16 + rr) * 128;
  }

  load_tile(0, 0); CPCOMMIT();
  load_tile(1, 1); CPCOMMIT();
  load_tile(2, 2); CPCOMMIT();

  int s = 0;
  for (int kt = 0; kt < NK; ++kt) {
    CPWAIT2();
    __syncthreads();
    const uint32_t sa = tiles + (uint32_t)s * STAGE_BYTES;
    const uint32_t sb = sa + 16384;
    #pragma unroll
    for (int ks = 0; ks < 4; ++ks) {
      const uint32_t pc = (uint32_t)(((ks * 2 + hi) ^ xr) << 4);
      uint32_t a[4][4], b[4][4];
      #pragma unroll
      for (int i = 0; i < 4; ++i) {
        asm volatile("ldmatrix.sync.aligned.m8n8.x4.shared.b16 {%0,%1,%2,%3}, [%4];"
          : "=r"(a[i][0]), "=r"(a[i][1]), "=r"(a[i][2]), "=r"(a[i][3])
          : "r"(sa + abase[i] + pc));
      }
      #pragma unroll
      for (int i = 0; i < 4; ++i) {
        asm volatile("ldmatrix.sync.aligned.m8n8.x4.shared.b16 {%0,%1,%2,%3}, [%4];"
          : "=r"(b[i][0]), "=r"(b[i][1]), "=r"(b[i][2]), "=r"(b[i][3])
          : "r"(sb + bbase[i] + pc));
      }
      #pragma unroll
      for (int im = 0; im < 4; ++im)
        #pragma unroll
        for (int in = 0; in < 8; ++in) {
          const uint32_t bb0 = b[in >> 1][in & 1];
          const uint32_t bb1 = b[in >> 1][(in & 1) + 2];
          asm volatile("mma.sync.aligned.m16n8k16.row.col.f32.bf16.bf16.f32 "
            "{%0,%1,%2,%3}, {%4,%5,%6,%7}, {%8,%9}, {%0,%1,%2,%3};"
            : "+f"(acc[im][in][0]), "+f"(acc[im][in][1]),
              "+f"(acc[im][in][2]), "+f"(acc[im][in][3])
            : "r"(a[im][0]), "r"(a[im][1]), "r"(a[im][2]), "r"(a[im][3]),
              "r"(bb0), "r"(bb1));
        }
    }
    __syncthreads();
    if (kt + 3 < NK) load_tile(s, kt + 3);
    CPCOMMIT();
    s = (s == 2) ? 0 : s + 1;
  }

  // ---------------- epilogues ----------------
  const int lr = lane >> 2, lc = (lane & 3) * 2;
  const int rbase = row0 + wm * 64;
  const int cbase = col0 + wn * 64;

  if (EPI == 0) {
    #pragma unroll
    for (int im = 0; im < 4; ++im) {
      float rs0 = 0.f, rs1 = 0.f;
      const int rA = rbase + im * 16 + lr;
      #pragma unroll
      for (int in = 0; in < 8; ++in) {
        float e0 = fexp(acc[im][in][0]);
        float e1 = fexp(acc[im][in][1]);
        float e2 = fexp(acc[im][in][2]);
        float e3 = fexp(acc[im][in][3]);
        const int cc2 = cbase + in * 8 + lc;
        *(__nv_bfloat162*)(g_E + (size_t)rA       * VOCAB + cc2) = __floats2bfloat162_rn(e0, e1);
        *(__nv_bfloat162*)(g_E + (size_t)(rA + 8) * VOCAB + cc2) = __floats2bfloat162_rn(e2, e3);
        rs0 += e0 + e1; rs1 += e2 + e3;
      }
      rs0 += __shfl_xor_sync(0xffffffffu, rs0, 1);
      rs0 += __shfl_xor_sync(0xffffffffu, rs0, 2);
      rs1 += __shfl_xor_sync(0xffffffffu, rs1, 1);
      rs1 += __shfl_xor_sync(0xffffffffu, rs1, 2);
      if ((lane & 3) == 0) {
        atomicAdd(&g_l[rA],     rs0);
        atomicAdd(&g_l[rA + 8], rs1);
      }
    }
  } else if (EPI == 1) {
    #pragma unroll
    for (int im = 0; im < 4; ++im) {
      const int rA = rbase + im * 16 + lr;
      const float inv0 = 1.f / g_l[rA];
      const float inv1 = 1.f / g_l[rA + 8];
      #pragma unroll
      for (int in = 0; in < 8; ++in) {
        const int cc2 = cbase + in * 8 + lc;
        *(__nv_bfloat162*)(g_Rb + (size_t)rA       * DIMD + cc2) =
          __floats2bfloat162_rn(acc[im][in][0] * inv0, acc[im][in][1] * inv0);
        *(__nv_bfloat162*)(g_Rb + (size_t)(rA + 8) * DIMD + cc2) =
          __floats2bfloat162_rn(acc[im][in][2] * inv1, acc[im][in][3] * inv1);
      }
    }
  } else {
    #pragma unroll
    for (int im = 0; im < 4; ++im) {
      const int rA = rbase + im * 16 + lr;
      #pragma unroll
      for (int in = 0; in < 8; ++in) {
        const int cc2 = cbase + in * 8 + lc;
        float2 x0 = *(const float2*)(Xf + (size_t)rA       * DIMD + cc2);
        float2 x1 = *(const float2*)(Xf + (size_t)(rA + 8) * DIMD + cc2);
        float2 b2 = *(const float2*)(bias + cc2);
        float2 o0, o1;
        o0.x = acc[im][in][0] + b2.x + x0.x;
        o0.y = acc[im][in][1] + b2.y + x0.y;
        o1.x = acc[im][in][2] + b2.x + x1.x;
        o1.y = acc[im][in][3] + b2.y + x1.y;
        *(float2*)(g_Y + (size_t)rA       * DIMD + cc2) = o0;
        *(float2*)(g_Y + (size_t)(rA + 8) * DIMD + cc2) = o1;
      }
    }
  }
}

// ---------------- layernorm ----------------
__global__ void k_ln(const float* __restrict__ gamma, const float* __restrict__ beta,
                     float* __restrict__ out) {
  int row  = blockIdx.x * 8 + (threadIdx.x >> 5);
  int lane = threadIdx.x & 31;
  const float* y = g_Y + (size_t)row * DIMD;
  float v[32], s = 0.f;
  #pragma unroll
  for (int i = 0; i < 32; ++i) { v[i] = y[lane + i * 32]; s += v[i]; }
  #pragma unroll
  for (int o = 16; o > 0; o >>= 1) s += __shfl_xor_sync(0xffffffffu, s, o);
  float mu = s * (1.f / DIMD);
  float q = 0.f;
  #pragma unroll
  for (int i = 0; i < 32; ++i) { float d = v[i] - mu; q += d * d; }
  #pragma unroll
  for (int o = 16; o > 0; o >>= 1) q += __shfl_xor_sync(0xffffffffu, q, o);
  float rstd = rsqrtf(q * (1.f / DIMD) + 1e-5f);
  #pragma unroll
  for (int i = 0; i < 32; ++i) {
    int cc = lane + i * 32;
    out[(size_t)row * DIMD + cc] = (v[i] - mu) * rstd * gamma[cc] + beta[cc];
  }
}

// ---------------- launch ----------------
extern "C" void kernel_launch(void* const* d_in, const int* in_sizes, int n_in,
                              void* d_out, int out_size) {
  const float* X     = (const float*)d_in[0];
  const float* T     = (const float*)d_in[1];
  const float* W     = (const float*)d_in[2];
  const float* bias  = (const float*)d_in[3];
  const float* gamma = (const float*)d_in[4];
  const float* beta  = (const float*)d_in[5];
  float* out = (float*)d_out;

  cudaFuncSetAttribute(k_g<0>, cudaFuncAttributeMaxDynamicSharedMemorySize, SMEM_DYN);
  cudaFuncSetAttribute(k_g<1>, cudaFuncAttributeMaxDynamicSharedMemorySize, SMEM_DYN);
  cudaFuncSetAttribute(k_g<2>, cudaFuncAttributeMaxDynamicSharedMemorySize, SMEM_DYN);

  k_cvt<<<2048, 512>>>(X, W);
  k_transpose<<<dim3(DIMD / 32, VOCAB / 32), dim3(32, 8)>>>(T);
  k_g<0><<<dim3(VOCAB / 256, M_ROWS / 128), 256, SMEM_DYN>>>(nullptr, nullptr);
  k_g<1><<<dim3(DIMD  / 256, M_ROWS / 128), 256, SMEM_DYN>>>(nullptr, nullptr);
  k_g<2><<<dim3(DIMD  / 256, M_ROWS / 128), 256, SMEM_DYN>>>(X, bias);
  k_ln<<<M_ROWS / 8, 256>>>(gamma, beta, out);
}